// round 7
// baseline (speedup 1.0000x reference)
#include <cuda_runtime.h>

#define KCLS 256
#define WARPS_PER_BLOCK 8
#define THREADS (WARPS_PER_BLOCK * 32)
#define CHUNK 4   // contiguous rows per warp

__device__ __forceinline__ float ex2f(float a) {
    float r; asm("ex2.approx.f32 %0, %1;" : "=f"(r) : "f"(a)); return r;
}
__device__ __forceinline__ float rcpf(float a) {
    float r; asm("rcp.approx.f32 %0, %1;" : "=f"(r) : "f"(a)); return r;
}

__global__ __launch_bounds__(THREADS, 4)
void dbf_kernel(const int* __restrict__ data,
                const float* __restrict__ t,
                const float4* __restrict__ noise,
                float4* __restrict__ out,
                int nrows)
{
    __shared__ __align__(16) float sg[KCLS];
    __shared__ __align__(16) float sh[KCLS];

    const int tid  = threadIdx.x;
    const int lane = tid & 31;
    const int warp = tid >> 5;

    // Closed-form Cholesky of C0 = (K+0.001) I - 11^T:
    //   T_k = a/(k-a), g_k = sqrt(a+T_k), h_k = T_k/g_k, a = K+0.001
    {
        const float ALPHA = 256.001f;
        float kf = (float)tid;
        float T  = ALPHA / (kf - ALPHA);
        float gg = sqrtf(ALPHA + T);
        sg[tid] = gg;
        sh[tid] = T / gg;
    }
    __syncthreads();

    const int kbase = lane * 8;

    // g/h slices hoisted to registers once per warp
    float4 ga = *(const float4*)&sg[kbase];
    float4 gb = *(const float4*)&sg[kbase + 4];
    float4 ha = *(const float4*)&sh[kbase];
    float4 hb = *(const float4*)&sh[kbase + 4];

    const float L2E = 1.4426950408889634f;
    const int gw      = blockIdx.x * WARPS_PER_BLOCK + warp;  // global warp id
    const int total_w = gridDim.x * WARPS_PER_BLOCK;

    for (int base = gw * CHUNK; base < nrows; base += total_w * CHUNK) {
        const int lim = (nrows - base < CHUNK) ? (nrows - base) : CHUNK;

        // Pointers for this chunk: everything advances by constants.
        const float*  tp = t + base;
        const int*    dp = data + base;
        const float4* np = noise + (size_t)base * (KCLS / 4) + lane * 2;
        float4*       op = out   + (size_t)base * (KCLS / 4) + lane * 2;

        // Prime pipeline: row 0 loads in flight
        float tv = __ldg(tp);
        int   x  = __ldg(dp);
        float4 n0 = __ldg(np + 0);
        float4 n1 = __ldg(np + 1);

        int r = 0;
        for (;;) {
            // ---- Prefetch next row (constant-offset addresses) ----
            const bool hn = (r + 1 < lim);
            float tv_n; int x_n; float4 m0, m1;
            if (hn) {
                tv_n = __ldg(tp + 1);
                x_n  = __ldg(dp + 1);
                m0   = __ldg(np + (KCLS / 4) + 0);
                m1   = __ldg(np + (KCLS / 4) + 1);
            }

            // ---- Compute current row ----
            float sb = fminf(tv, 1.0f - 1e-6f);
            sb = fmaxf(sb, 1e-10f);
            const float sb2 = sb * L2E;                 // sb * log2(e)
            const float kb2 = 256.0f * (sb * sb) * L2E; // K*beta*log2(e)
            // Row-uniform shift instead of exact max (softmax-invariant):
            // largest exponent = sb2*y - 40; overflow needs y > ~7.2 sigma.
            const float cofs = kb2 + 40.0f;

            float gv[8], hv[8];
            gv[0] = ga.x * n0.x;  hv[0] = ha.x * n0.x;
            gv[1] = ga.y * n0.y;  hv[1] = ha.y * n0.y;
            gv[2] = ga.z * n0.z;  hv[2] = ha.z * n0.z;
            gv[3] = ga.w * n0.w;  hv[3] = ha.w * n0.w;
            gv[4] = gb.x * n1.x;  hv[4] = hb.x * n1.x;
            gv[5] = gb.y * n1.y;  hv[5] = hb.y * n1.y;
            gv[6] = gb.z * n1.z;  hv[6] = hb.z * n1.z;
            gv[7] = gb.w * n1.w;  hv[7] = hb.w * n1.w;

            // Lane total of h*v (tree order)
            float run = ((hv[0] + hv[1]) + (hv[2] + hv[3]))
                      + ((hv[4] + hv[5]) + (hv[6] + hv[7]));

            // Warp inclusive scan of lane totals
            float inc = run;
            #pragma unroll
            for (int d = 1; d < 32; d <<= 1) {
                float nb = __shfl_up_sync(0xFFFFFFFFu, inc, d);
                if (lane >= d) inc += nb;
            }
            float run2 = inc - run;   // exclusive prefix

            // Fused prefix + logit + exp2
            float e[8];
            float s = 0.0f;
            #pragma unroll
            for (int i = 0; i < 8; i++) {
                float bias = (kbase + i == x) ? (kb2 - cofs) : -cofs;
                e[i] = ex2f(fmaf(sb2, gv[i] + run2, bias));
                run2 += hv[i];
                s += e[i];
            }

            // Warp sum
            #pragma unroll
            for (int d = 16; d >= 1; d >>= 1)
                s += __shfl_xor_sync(0xFFFFFFFFu, s, d);

            const float rr = rcpf(s);
            op[0] = make_float4(e[0]*rr, e[1]*rr, e[2]*rr, e[3]*rr);
            op[1] = make_float4(e[4]*rr, e[5]*rr, e[6]*rr, e[7]*rr);

            // ---- Rotate pipeline (constant pointer bumps) ----
            if (!hn) break;
            r++;
            tp += 1; dp += 1;
            np += (KCLS / 4); op += (KCLS / 4);
            tv = tv_n; x = x_n; n0 = m0; n1 = m1;
        }
    }
}

extern "C" void kernel_launch(void* const* d_in, const int* in_sizes, int n_in,
                              void* d_out, int out_size)
{
    const int*    data  = (const int*)d_in[0];
    const float*  t     = (const float*)d_in[1];
    const float4* noise = (const float4*)d_in[2];
    float4*       out   = (float4*)d_out;

    const int nrows = in_sizes[0];   // B*S = 16384
    const int rows_per_block = WARPS_PER_BLOCK * CHUNK;
    int blocks = (nrows + rows_per_block - 1) / rows_per_block;   // 512 for 16384
    dbf_kernel<<<blocks, THREADS>>>(data, t, noise, out, nrows);
}

// round 8
// speedup vs baseline: 1.1628x; 1.1628x over previous
#include <cuda_runtime.h>

#define KCLS 256
#define WARPS_PER_BLOCK 8
#define THREADS (WARPS_PER_BLOCK * 32)
#define BLOCKS_RESIDENT 740   // 5 blocks/SM * 148 SMs

__device__ __forceinline__ float ex2f(float a) {
    float r; asm("ex2.approx.f32 %0, %1;" : "=f"(r) : "f"(a)); return r;
}
__device__ __forceinline__ float rcpf(float a) {
    float r; asm("rcp.approx.f32 %0, %1;" : "=f"(r) : "f"(a)); return r;
}

// minBlocks=5 -> reg cap 51: small live set, 5 blocks/SM resident.
__global__ __launch_bounds__(THREADS, 5)
void dbf_kernel(const int* __restrict__ data,
                const float* __restrict__ t,
                const float4* __restrict__ noise,
                float4* __restrict__ out,
                int nrows)
{
    __shared__ __align__(16) float sg[KCLS];
    __shared__ __align__(16) float sh[KCLS];

    const int tid  = threadIdx.x;
    const int lane = tid & 31;
    const int warp = tid >> 5;

    // Closed-form Cholesky of C0 = (K+0.001) I - 11^T:
    //   T_k = a/(k-a), g_k = sqrt(a+T_k), h_k = T_k/g_k, a = K+0.001
    {
        const float ALPHA = 256.001f;
        float kf = (float)tid;
        float T  = ALPHA / (kf - ALPHA);
        float gg = sqrtf(ALPHA + T);
        sg[tid] = gg;
        sh[tid] = T / gg;
    }
    __syncthreads();

    const int kbase = lane * 8;
    const float L2E = 1.4426950408889634f;
    const int stride = gridDim.x * WARPS_PER_BLOCK;

    int row = blockIdx.x * WARPS_PER_BLOCK + warp;
    if (row >= nrows) return;

    // Prime the pipeline: current row's loads in flight
    float tv = __ldg(t + row);
    int   x  = __ldg(data + row);
    const float4* nrow = noise + (size_t)row * (KCLS / 4) + lane * 2;
    float4 n0 = __ldg(nrow + 0);
    float4 n1 = __ldg(nrow + 1);

    while (true) {
        // ---- Prefetch next row before touching current data ----
        const int  rnext = row + stride;
        const bool has_next = rnext < nrows;
        float tv_n; int x_n; float4 m0, m1;
        if (has_next) {
            tv_n = __ldg(t + rnext);
            x_n  = __ldg(data + rnext);
            const float4* nn = noise + (size_t)rnext * (KCLS / 4) + lane * 2;
            m0 = __ldg(nn + 0);
            m1 = __ldg(nn + 1);
        }

        // g/h from shared each iteration (keeps live set small; LDS latency
        // hides behind the pipeline). 4x LDS.128, conflict-free.
        float4 ga = *(const float4*)&sg[kbase];
        float4 gb = *(const float4*)&sg[kbase + 4];
        float4 ha = *(const float4*)&sh[kbase];
        float4 hb = *(const float4*)&sh[kbase + 4];

        // ---- Compute current row ----
        float sb = fminf(tv, 1.0f - 1e-6f);
        sb = fmaxf(sb, 1e-10f);
        const float sb2 = sb * L2E;                 // sb * log2(e)
        const float kb2 = 256.0f * (sb * sb) * L2E; // K*beta*log2(e)
        // Row-uniform shift instead of exact max (softmax-invariant):
        // largest exponent = sb2*y - 40; overflow needs y > ~7.2 sigma.
        const float cofs = kb2 + 40.0f;

        float gv[8], hv[8];
        gv[0] = ga.x * n0.x;  hv[0] = ha.x * n0.x;
        gv[1] = ga.y * n0.y;  hv[1] = ha.y * n0.y;
        gv[2] = ga.z * n0.z;  hv[2] = ha.z * n0.z;
        gv[3] = ga.w * n0.w;  hv[3] = ha.w * n0.w;
        gv[4] = gb.x * n1.x;  hv[4] = hb.x * n1.x;
        gv[5] = gb.y * n1.y;  hv[5] = hb.y * n1.y;
        gv[6] = gb.z * n1.z;  hv[6] = hb.z * n1.z;
        gv[7] = gb.w * n1.w;  hv[7] = hb.w * n1.w;

        // Lane total of h*v (tree order)
        float run = ((hv[0] + hv[1]) + (hv[2] + hv[3]))
                  + ((hv[4] + hv[5]) + (hv[6] + hv[7]));

        // Warp inclusive scan of lane totals
        float inc = run;
        #pragma unroll
        for (int d = 1; d < 32; d <<= 1) {
            float nb = __shfl_up_sync(0xFFFFFFFFu, inc, d);
            if (lane >= d) inc += nb;
        }
        float run2 = inc - run;   // exclusive prefix

        // Fused prefix + logit + exp2
        float e[8];
        float s = 0.0f;
        #pragma unroll
        for (int i = 0; i < 8; i++) {
            float bias = (kbase + i == x) ? (kb2 - cofs) : -cofs;
            e[i] = ex2f(fmaf(sb2, gv[i] + run2, bias));
            run2 += hv[i];
            s += e[i];
        }

        // Warp sum
        #pragma unroll
        for (int d = 16; d >= 1; d >>= 1)
            s += __shfl_xor_sync(0xFFFFFFFFu, s, d);

        const float rr = rcpf(s);
        float4* orow = out + (size_t)row * (KCLS / 4) + lane * 2;
        orow[0] = make_float4(e[0]*rr, e[1]*rr, e[2]*rr, e[3]*rr);
        orow[1] = make_float4(e[4]*rr, e[5]*rr, e[6]*rr, e[7]*rr);

        // ---- Rotate pipeline ----
        if (!has_next) break;
        row = rnext;
        tv = tv_n; x = x_n; n0 = m0; n1 = m1;
    }
}

extern "C" void kernel_launch(void* const* d_in, const int* in_sizes, int n_in,
                              void* d_out, int out_size)
{
    const int*    data  = (const int*)d_in[0];
    const float*  t     = (const float*)d_in[1];
    const float4* noise = (const float4*)d_in[2];
    float4*       out   = (float4*)d_out;

    const int nrows = in_sizes[0];   // B*S = 16384
    int blocks = (nrows + WARPS_PER_BLOCK - 1) / WARPS_PER_BLOCK;
    if (blocks > BLOCKS_RESIDENT) blocks = BLOCKS_RESIDENT;
    dbf_kernel<<<blocks, THREADS>>>(data, t, noise, out, nrows);
}

// round 9
// speedup vs baseline: 1.1662x; 1.0029x over previous
#include <cuda_runtime.h>

#define KCLS 256
#define WARPS_PER_BLOCK 8
#define THREADS (WARPS_PER_BLOCK * 32)
#define BLOCKS_RESIDENT 592   // 4 blocks/SM * 148 SMs (R6 best config)

__device__ __forceinline__ float ex2f(float a) {
    float r; asm("ex2.approx.f32 %0, %1;" : "=f"(r) : "f"(a)); return r;
}
__device__ __forceinline__ float rcpf(float a) {
    float r; asm("rcp.approx.f32 %0, %1;" : "=f"(r) : "f"(a)); return r;
}

__global__ __launch_bounds__(THREADS, 4)
void dbf_kernel(const int* __restrict__ data,
                const float* __restrict__ t,
                const float4* __restrict__ noise,
                float4* __restrict__ out,
                int nrows)
{
    __shared__ __align__(16) float sg[KCLS];
    __shared__ __align__(16) float sh[KCLS];

    const int tid  = threadIdx.x;
    const int lane = tid & 31;
    const int warp = tid >> 5;

    // Closed-form Cholesky of C0 = (K+0.001) I - 11^T:
    //   T_k = a/(k-a), g_k = sqrt(a+T_k), h_k = T_k/g_k, a = K+0.001
    {
        const float ALPHA = 256.001f;
        float kf = (float)tid;
        float T  = ALPHA / (kf - ALPHA);
        float gg = sqrtf(ALPHA + T);
        sg[tid] = gg;
        sh[tid] = T / gg;
    }
    __syncthreads();

    const int kbase = lane * 8;

    // g/h slices hoisted to registers once per warp (R6 best)
    float4 ga = *(const float4*)&sg[kbase];
    float4 gb = *(const float4*)&sg[kbase + 4];
    float4 ha = *(const float4*)&sh[kbase];
    float4 hb = *(const float4*)&sh[kbase + 4];

    const float L2E = 1.4426950408889634f;
    const int stride = gridDim.x * WARPS_PER_BLOCK;
    const int gw = blockIdx.x * WARPS_PER_BLOCK + warp;
    if (gw >= nrows) return;

    // Number of rows this warp handles (grid-stride, counted loop)
    int niter = (nrows - gw + stride - 1) / stride;

    // Strided pointers — advance by constants each iteration (no IMAD.WIDE)
    const float*  tp = t + gw;
    const int*    dp = data + gw;
    const float4* np = noise + (size_t)gw * (KCLS / 4) + lane * 2;
    float4*       op = out   + (size_t)gw * (KCLS / 4) + lane * 2;
    const size_t  nstep = (size_t)stride * (KCLS / 4);

    // Prime pipeline: row 0 loads in flight
    float tv = __ldg(tp);
    int   x  = __ldg(dp);
    float4 n0 = __ldg(np + 0);
    float4 n1 = __ldg(np + 1);

    for (int it = 0; it < niter; it++) {
        // ---- Prefetch next row (constant-stride addresses) ----
        const bool hn = (it + 1 < niter);
        float tv_n; int x_n; float4 m0, m1;
        if (hn) {
            tv_n = __ldg(tp + stride);
            x_n  = __ldg(dp + stride);
            m0   = __ldg(np + nstep + 0);
            m1   = __ldg(np + nstep + 1);
        }

        // ---- Per-row scalars ----
        float sb = fminf(tv, 1.0f - 1e-6f);
        sb = fmaxf(sb, 1e-10f);
        const float sb2 = sb * L2E;                 // sb * log2(e)
        const float kb2 = 256.0f * (sb * sb) * L2E; // K*beta*log2(e)
        // Row-uniform shift (softmax-invariant): exponents <= ~0 after -cofs.
        const float cofs = kb2 + 40.0f;

        float gv[8], hv[8];
        gv[0] = ga.x * n0.x;  hv[0] = ha.x * n0.x;
        gv[1] = ga.y * n0.y;  hv[1] = ha.y * n0.y;
        gv[2] = ga.z * n0.z;  hv[2] = ha.z * n0.z;
        gv[3] = ga.w * n0.w;  hv[3] = ha.w * n0.w;
        gv[4] = gb.x * n1.x;  hv[4] = hb.x * n1.x;
        gv[5] = gb.y * n1.y;  hv[5] = hb.y * n1.y;
        gv[6] = gb.z * n1.z;  hv[6] = hb.z * n1.z;
        gv[7] = gb.w * n1.w;  hv[7] = hb.w * n1.w;

        // ---- Lane-local pass: t_i = sb2*(gv_i + localPrefix_i) + bias_i ----
        // (no warp dependency; runs concurrently with the scan below)
        float f[8];
        float run = 0.0f;
        float m = -3.4e38f;
        #pragma unroll
        for (int i = 0; i < 8; i++) {
            float bias = (kbase + i == x) ? kb2 : 0.0f;
            float ti = fmaf(sb2, gv[i] + run, bias);
            run += hv[i];
            f[i] = ti;
            m = fmaxf(m, ti);
        }

        // ---- Warp inclusive scan of lane totals (SHFL chain) ----
        float inc = run;
        #pragma unroll
        for (int d = 1; d < 32; d <<= 1) {
            float nb = __shfl_up_sync(0xFFFFFFFFu, inc, d);
            if (lane >= d) inc += nb;
        }
        const float excl = inc - run;

        // ---- Lane-local exp (overlaps scan latency) ----
        float sf = 0.0f;
        #pragma unroll
        for (int i = 0; i < 8; i++) {
            f[i] = ex2f(f[i] - m);   // f_i in (0,1]
            sf += f[i];
        }

        // ---- Stitch: e_i = f_i * 2^u,  u = m + sb2*excl - cofs = max lg <= ~0
        const float u  = fmaf(sb2, excl, m - cofs);
        const float wq = ex2f(u);
        float s = sf * wq;

        // Warp sum
        #pragma unroll
        for (int d = 16; d >= 1; d >>= 1)
            s += __shfl_xor_sync(0xFFFFFFFFu, s, d);

        const float scale = wq * rcpf(s);
        op[0] = make_float4(f[0]*scale, f[1]*scale, f[2]*scale, f[3]*scale);
        op[1] = make_float4(f[4]*scale, f[5]*scale, f[6]*scale, f[7]*scale);

        // ---- Rotate pipeline (constant pointer bumps) ----
        if (!hn) break;
        tp += stride; dp += stride; np += nstep; op += nstep;
        tv = tv_n; x = x_n; n0 = m0; n1 = m1;
    }
}

extern "C" void kernel_launch(void* const* d_in, const int* in_sizes, int n_in,
                              void* d_out, int out_size)
{
    const int*    data  = (const int*)d_in[0];
    const float*  t     = (const float*)d_in[1];
    const float4* noise = (const float4*)d_in[2];
    float4*       out   = (float4*)d_out;

    const int nrows = in_sizes[0];   // B*S = 16384
    int blocks = (nrows + WARPS_PER_BLOCK - 1) / WARPS_PER_BLOCK;
    if (blocks > BLOCKS_RESIDENT) blocks = BLOCKS_RESIDENT;
    dbf_kernel<<<blocks, THREADS>>>(data, t, noise, out, nrows);
}